// round 2
// baseline (speedup 1.0000x reference)
#include <cuda_runtime.h>

// Problem constants: LX=8, LY=4, D=4, PHYS=2, batch=128
// vec length = 2 * 8 * 4^5 = 16384 ; per-x block = 1024
#define NB   128
#define NCOL 16384

// Scratch (device globals: no allocation allowed)
__device__ __align__(16) float g_H[NB * 64];
__device__ __align__(16) float g_C[NB * NCOL];

// ---------------------------------------------------------------------------
// Kernel 1: H[b, j] = relu(b1[j] + sum_k cfg[b,k] * W1[k,j])   (128 x 64)
// ---------------------------------------------------------------------------
__global__ void k_hidden(const int* __restrict__ cfg,
                         const float* __restrict__ W1,
                         const float* __restrict__ b1) {
    int b = blockIdx.x;
    int j = threadIdx.x;            // 64 threads
    float acc = b1[j];
#pragma unroll
    for (int k = 0; k < 32; k++)
        acc = fmaf((float)cfg[b * 32 + k], W1[k * 64 + j], acc);
    g_H[b * 64 + j] = fmaxf(acc, 0.0f);
}

// ---------------------------------------------------------------------------
// Kernel 2: C[b, n] = 0.001 * (b2[n] + sum_k H[b,k] * W2[k,n])
// 128 x 16384 x 64 GEMM. Each thread: 1 column x 16 batches (register block).
// grid = (16384/256, 128/16) = (64, 8), block = 256.
// W2 row-major (64, 16384): W2[k*16384 + n] is coalesced across threads.
// ---------------------------------------------------------------------------
__global__ void k_gemm(const float* __restrict__ W2,
                       const float* __restrict__ b2) {
    __shared__ float Hs[16 * 64];
    int n  = blockIdx.x * 256 + threadIdx.x;
    int b0 = blockIdx.y * 16;

    for (int i = threadIdx.x; i < 16 * 64; i += 256)
        Hs[i] = g_H[b0 * 64 + i];
    __syncthreads();

    float bias = b2[n];
    float acc[16];
#pragma unroll
    for (int i = 0; i < 16; i++) acc[i] = bias;

#pragma unroll 4
    for (int k = 0; k < 64; k++) {
        float w = W2[k * NCOL + n];
#pragma unroll
        for (int i = 0; i < 16; i++)
            acc[i] = fmaf(Hs[i * 64 + k], w, acc[i]);   // Hs broadcast read
    }
#pragma unroll
    for (int i = 0; i < 16; i++)
        g_C[(b0 + i) * NCOL + n] = 0.001f * acc[i];
}

// ---------------------------------------------------------------------------
// Kernel 3: per-batch tensor-network contraction + transfer-matrix chain.
// One block (256 threads) per batch element.
//
// A layout (row-major): A[x][y][a][b][c][d][p], strides:
//   x:2048  y:512  a:128  b:32  c:8  d:2  p:1
// s_y[t] with t = a*64 + b*16 + c*4 + d  -> A[x*2048 + y*512 + t*2 + p]
//
// bot2[i][j][U] = sum_u s0[l,r,(d=0),u] * s1[L,R,(d=u),U] + C[b, x*1024 + (i*16+j)*4 + U]
// top2[i][j][d] = sum_u s2[l,r,d,u]     * s3[L,R,(d'=u),(u'=0)] + C[b, 8192 + ...]
//   (i = l*4+L, j = r*4+R)
//
// Chain: V' (16x16) = sum_u T_u^T V S_u with T_u[i,j]=bot2[i,j,u], S_u[I,J]=top2[I,J,u]
// Output: V_final[0,0].
// ---------------------------------------------------------------------------
__global__ void k_chain(const int* __restrict__ cfg,
                        const float* __restrict__ A,
                        float* __restrict__ out) {
    __shared__ float s0[256], s1[256], s2[256], s3[256];
    __shared__ float bot[4][256];   // [u][i*16+j]
    __shared__ float top[4][256];   // [d][i*16+j]
    __shared__ float V[256];        // V[i*16+I]
    __shared__ float P4[4][256];    // [u][j*16+I]
    __shared__ int   c[32];

    int b = blockIdx.x;
    int t = threadIdx.x;

    if (t < 32) c[t] = cfg[b * 32 + t];
    V[t] = (t == 0) ? 1.0f : 0.0f;
    __syncthreads();

    const float* Crow = g_C + b * NCOL;

    int i = t >> 4, j = t & 15;
    int l = i >> 2, L = i & 3, r = j >> 2, R = j & 3;
    int j2 = t >> 4, I = t & 15;   // roles in the V-update phase
    int J = I;

    for (int x = 0; x < 8; x++) {
        // ---- stage the four selected A slices into smem ----
        const float* Ax = A + x * 2048;
        s0[t] = Ax[          t * 2 + c[x * 4 + 0]];
        s1[t] = Ax[ 512    + t * 2 + c[x * 4 + 1]];
        s2[t] = Ax[ 1024   + t * 2 + c[x * 4 + 2]];
        s3[t] = Ax[ 1536   + t * 2 + c[x * 4 + 3]];
        __syncthreads();

        // ---- build bot2 / top2 (+ NN correction) ----
        float4 cb = *(const float4*)(Crow + x * 1024 + t * 4);
        float4 ct = *(const float4*)(Crow + 8192 + x * 1024 + t * 4);

        float r0v[4], r3v[4];
#pragma unroll
        for (int u = 0; u < 4; u++) {
            r0v[u] = s0[l * 64 + r * 16 + u];          // s0[l,r,0,u]
            r3v[u] = s3[L * 64 + R * 16 + u * 4];      // s3[L,R,u,0]
        }
#pragma unroll
        for (int U = 0; U < 4; U++) {
            float a0 = 0.0f;
#pragma unroll
            for (int u = 0; u < 4; u++)
                a0 = fmaf(r0v[u], s1[L * 64 + R * 16 + u * 4 + U], a0);
            bot[U][t] = a0 + ((const float*)&cb)[U];
        }
#pragma unroll
        for (int d = 0; d < 4; d++) {
            float a0 = 0.0f;
#pragma unroll
            for (int u = 0; u < 4; u++)
                a0 = fmaf(s2[l * 64 + r * 16 + d * 4 + u], r3v[u], a0);
            top[d][t] = a0 + ((const float*)&ct)[d];
        }
        __syncthreads();

        // ---- V update: P_u[j,I] = sum_i T_u[i,j] V[i,I] ----
        float vload[16];
#pragma unroll
        for (int ii = 0; ii < 16; ii++) vload[ii] = V[ii * 16 + I];
#pragma unroll
        for (int u = 0; u < 4; u++) {
            float p = 0.0f;
#pragma unroll
            for (int ii = 0; ii < 16; ii++)
                p = fmaf(bot[u][ii * 16 + j2], vload[ii], p);  // bot broadcast
            P4[u][t] = p;
        }
        __syncthreads();

        // ---- V'[j,J] = sum_u sum_I P_u[j,I] S_u[I,J] ----
        float acc = 0.0f;
#pragma unroll
        for (int u = 0; u < 4; u++) {
#pragma unroll
            for (int I2 = 0; I2 < 16; I2++)
                acc = fmaf(P4[u][j2 * 16 + I2], top[u][I2 * 16 + J], acc);
        }
        __syncthreads();
        V[t] = acc;
        __syncthreads();
    }

    if (t == 0) out[b] = V[0];
}

// ---------------------------------------------------------------------------
extern "C" void kernel_launch(void* const* d_in, const int* in_sizes, int n_in,
                              void* d_out, int out_size) {
    const int*   cfg = (const int*)d_in[0];
    const float* A   = (const float*)d_in[1];
    const float* W1  = (const float*)d_in[2];
    const float* b1  = (const float*)d_in[3];
    const float* W2  = (const float*)d_in[4];
    const float* b2  = (const float*)d_in[5];
    float* out = (float*)d_out;

    k_hidden<<<NB, 64>>>(cfg, W1, b1);
    k_gemm<<<dim3(NCOL / 256, NB / 16), 256>>>(W2, b2);
    k_chain<<<NB, 256>>>(cfg, A, out);
}

// round 3
// speedup vs baseline: 1.1232x; 1.1232x over previous
#include <cuda_runtime.h>

// Problem constants: LX=8, LY=4, D=4, PHYS=2, batch=128
#define NB   128
#define NCOL 16384

// Scratch (device global: no allocation allowed)
__device__ __align__(16) float g_C[NB * NCOL];

// f32x2 packed helpers (sm_100+ PTX)
#define FMA2(d, a, b) asm("fma.rn.f32x2 %0, %1, %2, %0;" : "+l"(d) : "l"(a), "l"(b))
#define PACK2(d, lo, hi) asm("mov.b64 %0, {%1, %2};" : "=l"(d) : "f"(lo), "f"(hi))
#define UNPACK2(lo, hi, s) asm("mov.b64 {%0, %1}, %2;" : "=f"(lo), "=f"(hi) : "l"(s))

// ---------------------------------------------------------------------------
// Kernel 1 (fused hidden + gemm):
//   H[b,k] = relu(b1[k] + cfg[b,:]·W1[:,k])           (computed per block)
//   C[b,n] = 0.001 * (b2[n] + H[b,:]·W2[:,n])
// grid (32, 4): block covers 512 columns x 32 batches; 128 blocks = 1 wave.
// Batch pairs packed into f32x2 accumulators -> FFMA2 at 128 FMA/cyc/SM.
// ---------------------------------------------------------------------------
__global__ void __launch_bounds__(512, 1)
k_gemm(const int* __restrict__ cfg,
       const float* __restrict__ W1,
       const float* __restrict__ b1,
       const float* __restrict__ W2,
       const float* __restrict__ b2) {
    __shared__ __align__(16) float Hs[64 * 32];   // [k][b_local], pairs adjacent
    __shared__ int cs[32 * 32];                    // [b_local][k]

    const int tid = threadIdx.x;
    const int n   = blockIdx.x * 512 + tid;
    const int b0  = blockIdx.y * 32;

    // stage cfg for this block's 32 batches
    for (int idx = tid; idx < 32 * 32; idx += 512)
        cs[idx] = cfg[b0 * 32 + idx];
    __syncthreads();

    // hidden layer: thread owns hidden index j = tid & 63, 4 batches
    {
        const int j = tid & 63;
        float w1c[32];
#pragma unroll
        for (int k = 0; k < 32; k++) w1c[k] = W1[k * 64 + j];
        const float bj = b1[j];
#pragma unroll
        for (int m = 0; m < 4; m++) {
            const int bl = (tid >> 6) + 8 * m;
            float acc = bj;
#pragma unroll
            for (int k = 0; k < 32; k++)
                acc = fmaf((float)cs[bl * 32 + k], w1c[k], acc);
            Hs[j * 32 + bl] = fmaxf(acc, 0.0f);
        }
    }
    __syncthreads();

    // main GEMM: 16 f32x2 accumulators = 32 batches
    unsigned long long acc[16];
    {
        const float bias = b2[n];
        unsigned long long bias2;
        PACK2(bias2, bias, bias);
#pragma unroll
        for (int q = 0; q < 16; q++) acc[q] = bias2;
    }

#pragma unroll 4
    for (int k = 0; k < 64; k++) {
        const float w = W2[k * NCOL + n];
        unsigned long long w2p;
        PACK2(w2p, w, w);
        const ulonglong2* hp = (const ulonglong2*)(Hs + k * 32);
#pragma unroll
        for (int q = 0; q < 8; q++) {
            ulonglong2 h = hp[q];
            FMA2(acc[2 * q],     h.x, w2p);
            FMA2(acc[2 * q + 1], h.y, w2p);
        }
    }

#pragma unroll
    for (int q = 0; q < 16; q++) {
        float lo, hi;
        UNPACK2(lo, hi, acc[q]);
        g_C[(b0 + 2 * q)     * NCOL + n] = 0.001f * lo;
        g_C[(b0 + 2 * q + 1) * NCOL + n] = 0.001f * hi;
    }
}

// ---------------------------------------------------------------------------
// Kernel 2: per-batch tensor assembly + transfer-matrix chain.
// One block (256 threads) per batch.
//
// bot_u[i,j], top_u[I,J] stored TRANSPOSED with stride 20:
//   botT[u][j*20 + i], topT[u][J*20 + I]  -> column reads become LDS.128.
// V stored transposed stride 17: VT[col*17 + row] -> conflict-free column read.
// P4[u][j*16 + I] row-major -> LDS.128 row reads.
//
// Chain: P_u[j,I] = sum_i bot_u[i,j] V[i,I];  V'[j,J] = sum_{u,I} P_u[j,I] top_u[I,J]
// ---------------------------------------------------------------------------
__global__ void __launch_bounds__(256, 1)
k_chain(const int* __restrict__ cfg,
        const float* __restrict__ A,
        float* __restrict__ out) {
    __shared__ float s0[256], s1[256], s2[256], s3[256];
    __shared__ __align__(16) float botT[4][320];
    __shared__ __align__(16) float topT[4][320];
    __shared__ __align__(16) float P4[4][256];
    __shared__ float VT[288];
    __shared__ int   c[32];

    const int b = blockIdx.x;
    const int t = threadIdx.x;

    if (t < 32) c[t] = cfg[b * 32 + t];
    VT[t] = 0.0f;
    if (t < 32) VT[256 + t] = 0.0f;
    __syncthreads();
    if (t == 0) VT[0] = 1.0f;   // V[0,0] = 1 (VT[0*17+0])

    const float* Crow = g_C + b * NCOL;

    const int i = t >> 4, j = t & 15;
    const int l = i >> 2, L = i & 3, r = j >> 2, R = j & 3;
    const int j2 = t >> 4, I = t & 15;   // roles in chain phases (J == I slot)

    float accOut = 0.0f;

    for (int x = 0; x < 8; x++) {
        // ---- stage selected A slices ----
        const float* Ax = A + x * 2048;
        s0[t] = Ax[         t * 2 + c[x * 4 + 0]];
        s1[t] = Ax[ 512   + t * 2 + c[x * 4 + 1]];
        s2[t] = Ax[1024   + t * 2 + c[x * 4 + 2]];
        s3[t] = Ax[1536   + t * 2 + c[x * 4 + 3]];
        __syncthreads();   // also orders prev-iter VT writes before P reads

        // ---- build bot/top (+ NN correction), stored transposed ----
        float4 cb = *(const float4*)(Crow + x * 1024 + t * 4);
        float4 ct = *(const float4*)(Crow + 8192 + x * 1024 + t * 4);

        float r0v[4], r3v[4];
#pragma unroll
        for (int u = 0; u < 4; u++) {
            r0v[u] = s0[l * 64 + r * 16 + u];       // s0[l,r,0,u]
            r3v[u] = s3[L * 64 + R * 16 + u * 4];   // s3[L,R,u,0]
        }
#pragma unroll
        for (int U = 0; U < 4; U++) {
            float a0 = 0.0f;
#pragma unroll
            for (int u = 0; u < 4; u++)
                a0 = fmaf(r0v[u], s1[L * 64 + R * 16 + u * 4 + U], a0);
            botT[U][j * 20 + i] = a0 + ((const float*)&cb)[U];
        }
#pragma unroll
        for (int d = 0; d < 4; d++) {
            float a0 = 0.0f;
#pragma unroll
            for (int u = 0; u < 4; u++)
                a0 = fmaf(s2[l * 64 + r * 16 + d * 4 + u], r3v[u], a0);
            topT[d][j * 20 + i] = a0 + ((const float*)&ct)[d];
        }
        __syncthreads();

        // ---- P phase: P_u[j2, I] = sum_ii bot_u[ii, j2] * V[ii, I] ----
        float vl[16];
#pragma unroll
        for (int ii = 0; ii < 16; ii++) vl[ii] = VT[I * 17 + ii];
#pragma unroll
        for (int u = 0; u < 4; u++) {
            const float4* bp = (const float4*)&botT[u][j2 * 20];
            float p = 0.0f;
#pragma unroll
            for (int q = 0; q < 4; q++) {
                float4 b4 = bp[q];
                p = fmaf(b4.x, vl[4 * q + 0], p);
                p = fmaf(b4.y, vl[4 * q + 1], p);
                p = fmaf(b4.z, vl[4 * q + 2], p);
                p = fmaf(b4.w, vl[4 * q + 3], p);
            }
            P4[u][j2 * 16 + I] = p;
        }
        __syncthreads();

        // ---- V' phase: V'[j2, J] = sum_u sum_I2 P_u[j2, I2] * top_u[I2, J] ----
        float acc = 0.0f;
#pragma unroll
        for (int u = 0; u < 4; u++) {
            const float4* pp = (const float4*)&P4[u][j2 * 16];
            const float4* tp = (const float4*)&topT[u][I * 20];   // J == I
#pragma unroll
            for (int q = 0; q < 4; q++) {
                float4 p4 = pp[q];
                float4 t4 = tp[q];
                acc = fmaf(p4.x, t4.x, acc);
                acc = fmaf(p4.y, t4.y, acc);
                acc = fmaf(p4.z, t4.z, acc);
                acc = fmaf(p4.w, t4.w, acc);
            }
        }
        __syncthreads();                // all P4/topT reads done before overwrite
        VT[I * 17 + j2] = acc;          // VT[col=J][row=j]  (next iter synced by staging barrier)
        accOut = acc;
    }

    if (t == 0) out[b] = accOut;        // thread 0 owns (j=0, J=0)
}

// ---------------------------------------------------------------------------
extern "C" void kernel_launch(void* const* d_in, const int* in_sizes, int n_in,
                              void* d_out, int out_size) {
    const int*   cfg = (const int*)d_in[0];
    const float* A   = (const float*)d_in[1];
    const float* W1  = (const float*)d_in[2];
    const float* b1  = (const float*)d_in[3];
    const float* W2  = (const float*)d_in[4];
    const float* b2  = (const float*)d_in[5];
    float* out = (float*)d_out;

    k_gemm<<<dim3(32, 4), 512>>>(cfg, W1, b1, W2, b2);
    k_chain<<<NB, 256>>>(cfg, A, out);
}